// round 1
// baseline (speedup 1.0000x reference)
#include <cuda_runtime.h>
#include <math.h>

#define Nn 50000
#define Ee 1600000
#define Gg 64

// ---------------- device scratch (no dynamic allocation allowed) ----------------
__device__ float g_h[Nn*64];        // node features (updated in place per layer)
__device__ float g_Q[Nn*64];
__device__ float g_K[Nn*64];
__device__ float g_V[Nn*64];
__device__ float g_S[Nn*64];        // skip = h @ Ws + bs
__device__ int   g_deg[Nn];
__device__ int   g_rowptr[Nn+1];
__device__ int   g_cursor[Nn];
__device__ int   g_srcperm[Ee];     // src node id, CSR(dst)-ordered
__device__ float g_eattr[Ee*16];    // edge_attr permuted into CSR(dst) order
__device__ float g_pool[Gg*64];
__device__ int   g_cnt[Gg];

// ---------------- zero the accumulators ----------------
__global__ void zero_kernel() {
    int i = blockIdx.x * blockDim.x + threadIdx.x;
    const int total = Nn + Gg + Gg*64;
    for (; i < total; i += gridDim.x * blockDim.x) {
        if (i < Nn)            g_deg[i] = 0;
        else if (i < Nn + Gg)  g_cnt[i - Nn] = 0;
        else                   g_pool[i - Nn - Gg] = 0.f;
    }
}

// ---------------- degree histogram over dst ----------------
__global__ void hist_kernel(const int* __restrict__ dst) {
    int e = blockIdx.x * blockDim.x + threadIdx.x;
    if (e < Ee) atomicAdd(&g_deg[dst[e]], 1);
}

// ---------------- single-block exclusive scan -> rowptr, cursor ----------------
__global__ void scan_kernel() {
    __shared__ int sh[1024];
    __shared__ int carry;
    if (threadIdx.x == 0) carry = 0;
    __syncthreads();
    for (int base = 0; base < Nn; base += 1024) {
        int i = base + threadIdx.x;
        int v = (i < Nn) ? g_deg[i] : 0;
        sh[threadIdx.x] = v;
        __syncthreads();
        for (int off = 1; off < 1024; off <<= 1) {
            int t = (threadIdx.x >= (unsigned)off) ? sh[threadIdx.x - off] : 0;
            __syncthreads();
            sh[threadIdx.x] += t;
            __syncthreads();
        }
        int excl = carry + sh[threadIdx.x] - v;
        if (i < Nn) { g_rowptr[i] = excl; g_cursor[i] = excl; }
        __syncthreads();
        if (threadIdx.x == 0) carry += sh[1023];
        __syncthreads();
    }
    if (threadIdx.x == 0) g_rowptr[Nn] = carry;
}

// ---------------- scatter edges into CSR(dst) order ----------------
__global__ void scatter_kernel(const int* __restrict__ src,
                               const int* __restrict__ dst,
                               const float* __restrict__ ea) {
    int e = blockIdx.x * blockDim.x + threadIdx.x;
    if (e >= Ee) return;
    int d = dst[e];
    int p = atomicAdd(&g_cursor[d], 1);
    g_srcperm[p] = src[e];
    const float4* s = (const float4*)(ea + (size_t)e * 16);
    float4* o = (float4*)(g_eattr + (size_t)p * 16);
    o[0] = s[0]; o[1] = s[1]; o[2] = s[2]; o[3] = s[3];
}

// ---------------- input node MLP: h = relu(x @ Wn + bn), 32 -> 64 ----------------
__global__ void node_in_kernel(const float* __restrict__ x,
                               const float* __restrict__ Wn,
                               const float* __restrict__ bn) {
    __shared__ float Wsm[32*64];
    __shared__ float bsm[64];
    __shared__ float rows[4*32];
    for (int i = threadIdx.x; i < 32*64; i += 256) Wsm[i] = Wn[i];
    if (threadIdx.x < 64) bsm[threadIdx.x] = bn[threadIdx.x];
    int c = threadIdx.x & 63, sub = threadIdx.x >> 6;
    int base = blockIdx.x * 64;
    for (int g = 0; g < 16; g++) {
        __syncthreads();
        if (threadIdx.x < 128) {
            int node = base + g*4 + (threadIdx.x >> 5);
            if (node < Nn) rows[threadIdx.x] = x[node*32 + (threadIdx.x & 31)];
        }
        __syncthreads();
        int node = base + g*4 + sub;
        if (node < Nn) {
            float acc = bsm[c];
            #pragma unroll
            for (int k = 0; k < 32; k++) acc = fmaf(rows[sub*32 + k], Wsm[k*64 + c], acc);
            g_h[node*64 + c] = fmaxf(acc, 0.f);
        }
    }
}

// ---------------- 64x64 linear: out[sel] = g_h @ W + b ----------------
__global__ void lin64_kernel(const float* __restrict__ W,
                             const float* __restrict__ b, int sel) {
    __shared__ float Wsm[64*64];
    __shared__ float bsm[64];
    __shared__ float rows[4*64];
    for (int i = threadIdx.x; i < 64*64; i += 256) Wsm[i] = W[i];
    if (threadIdx.x < 64) bsm[threadIdx.x] = b[threadIdx.x];
    float* out = (sel == 0) ? g_Q : (sel == 1) ? g_K : (sel == 2) ? g_V : g_S;
    int c = threadIdx.x & 63, sub = threadIdx.x >> 6;
    int base = blockIdx.x * 64;
    for (int g = 0; g < 16; g++) {
        __syncthreads();
        int node = base + g*4 + sub;
        if (node < Nn) rows[threadIdx.x] = g_h[node*64 + c];
        __syncthreads();
        if (node < Nn) {
            float acc = bsm[c];
            #pragma unroll
            for (int k = 0; k < 64; k++) acc = fmaf(rows[sub*64 + k], Wsm[k*64 + c], acc);
            out[node*64 + c] = acc;
        }
    }
}

// ---------------- attention: one warp per dst node, online softmax ----------------
// lane l handles channels 2l, 2l+1; head = l/8 (C=16 channels = 8 lanes)
__global__ void attn_kernel(const float* __restrict__ Wel) {
    int wid  = (blockIdx.x * blockDim.x + threadIdx.x) >> 5;
    int lane = threadIdx.x & 31;
    if (wid >= Nn) return;

    // We[:, 2l:2l+2] held in registers (16 x float2)
    float2 wr[16];
    #pragma unroll
    for (int j = 0; j < 16; j++) wr[j] = *(const float2*)(Wel + j*64 + 2*lane);

    float2 q = *(const float2*)(g_Q + (size_t)wid*64 + 2*lane);
    int beg = g_rowptr[wid], end = g_rowptr[wid + 1];

    float m = -INFINITY, dsum = 0.f, ax = 0.f, ay = 0.f;
    for (int i = beg; i < end; i++) {
        int s = g_srcperm[i];
        const float4* ea4 = (const float4*)(g_eattr + (size_t)i * 16);
        float4 a0 = ea4[0], a1 = ea4[1], a2 = ea4[2], a3 = ea4[3];
        float2 kv = *(const float2*)(g_K + (size_t)s*64 + 2*lane);
        float2 vv = *(const float2*)(g_V + (size_t)s*64 + 2*lane);

        float ea[16] = {a0.x,a0.y,a0.z,a0.w, a1.x,a1.y,a1.z,a1.w,
                        a2.x,a2.y,a2.z,a2.w, a3.x,a3.y,a3.z,a3.w};
        float e0 = 0.f, e1 = 0.f;
        #pragma unroll
        for (int j = 0; j < 16; j++) {
            e0 = fmaf(ea[j], wr[j].x, e0);
            e1 = fmaf(ea[j], wr[j].y, e1);
        }
        kv.x += e0; kv.y += e1;
        vv.x += e0; vv.y += e1;

        float p = q.x * kv.x + q.y * kv.y;
        p += __shfl_xor_sync(0xffffffffu, p, 1);
        p += __shfl_xor_sync(0xffffffffu, p, 2);
        p += __shfl_xor_sync(0xffffffffu, p, 4);
        float alpha = p * 0.25f;   // 1/sqrt(C), C=16

        float mn   = fmaxf(m, alpha);
        float corr = __expf(m - mn);
        float w    = __expf(alpha - mn);
        dsum = dsum * corr + w;
        ax   = ax * corr + w * vv.x;
        ay   = ay * corr + w * vv.y;
        m = mn;
    }
    float inv = 1.f / (dsum + 1e-16f);
    float2 sv = *(const float2*)(g_S + (size_t)wid*64 + 2*lane);
    float o0 = fmaxf(fmaf(ax, inv, sv.x), 0.f);
    float o1 = fmaxf(fmaf(ay, inv, sv.y), 0.f);
    float2* hp = (float2*)(g_h + (size_t)wid*64 + 2*lane);
    float2 hv = *hp;
    hv.x += o0; hv.y += o1;
    *hp = hv;
}

// ---------------- global mean pool (sum + count via atomics) ----------------
__global__ void pool_kernel(const int* __restrict__ batch) {
    int i = blockIdx.x * blockDim.x + threadIdx.x;
    if (i >= Nn*64) return;
    int n = i >> 6, c = i & 63;
    int g = batch[n];
    atomicAdd(&g_pool[g*64 + c], g_h[i]);
    if (c == 0) atomicAdd(&g_cnt[g], 1);
}

// ---------------- head MLP: out = relu(pooled @ W1 + b1) @ W2 + b2 ----------------
__global__ void final_kernel(const float* __restrict__ W1, const float* __restrict__ b1,
                             const float* __restrict__ W2, const float* __restrict__ b2,
                             float* __restrict__ out) {
    int g = blockIdx.x;
    int j = threadIdx.x;   // 32 hidden units
    float invc = 1.f / fmaxf((float)g_cnt[g], 1.f);
    float acc = b1[j];
    #pragma unroll
    for (int k = 0; k < 64; k++)
        acc = fmaf(g_pool[g*64 + k] * invc, W1[k*32 + j], acc);
    acc = fmaxf(acc, 0.f);
    float t = acc * W2[j];
    #pragma unroll
    for (int o = 16; o > 0; o >>= 1) t += __shfl_xor_sync(0xffffffffu, t, o);
    if (j == 0) out[g] = t + b2[0];
}

// ---------------- launch ----------------
extern "C" void kernel_launch(void* const* d_in, const int* in_sizes, int n_in,
                              void* d_out, int out_size) {
    const float* x     = (const float*)d_in[0];
    const int*   ei    = (const int*)  d_in[1];
    const float* eattr = (const float*)d_in[2];
    const int*   batch = (const int*)  d_in[3];
    const float* Wn = (const float*)d_in[4];  const float* bn = (const float*)d_in[5];
    const float* Wq = (const float*)d_in[6];  const float* bq = (const float*)d_in[7];
    const float* Wk = (const float*)d_in[8];  const float* bk = (const float*)d_in[9];
    const float* Wv = (const float*)d_in[10]; const float* bv = (const float*)d_in[11];
    const float* We = (const float*)d_in[12];
    const float* Ws = (const float*)d_in[13]; const float* bs = (const float*)d_in[14];
    const float* W1 = (const float*)d_in[15]; const float* b1 = (const float*)d_in[16];
    const float* W2 = (const float*)d_in[17]; const float* b2 = (const float*)d_in[18];
    float* out = (float*)d_out;

    const int* src = ei;        // edge_index[0]
    const int* dst = ei + Ee;   // edge_index[1]

    zero_kernel<<<64, 256>>>();
    hist_kernel<<<(Ee + 255)/256, 256>>>(dst);
    scan_kernel<<<1, 1024>>>();
    scatter_kernel<<<(Ee + 255)/256, 256>>>(src, dst, eattr);
    node_in_kernel<<<(Nn + 63)/64, 256>>>(x, Wn, bn);

    for (int l = 0; l < 3; l++) {
        const float* Wql = Wq + (size_t)l*64*64; const float* bql = bq + (size_t)l*64;
        const float* Wkl = Wk + (size_t)l*64*64; const float* bkl = bk + (size_t)l*64;
        const float* Wvl = Wv + (size_t)l*64*64; const float* bvl = bv + (size_t)l*64;
        const float* Wsl = Ws + (size_t)l*64*64; const float* bsl = bs + (size_t)l*64;
        const float* Wel = We + (size_t)l*16*64;
        int gb = (Nn + 63) / 64;
        lin64_kernel<<<gb, 256>>>(Wql, bql, 0);
        lin64_kernel<<<gb, 256>>>(Wkl, bkl, 1);
        lin64_kernel<<<gb, 256>>>(Wvl, bvl, 2);
        lin64_kernel<<<gb, 256>>>(Wsl, bsl, 3);
        attn_kernel<<<(Nn*32 + 255)/256, 256>>>(Wel);
    }

    pool_kernel<<<(Nn*64 + 255)/256, 256>>>(batch);
    final_kernel<<<Gg, 32>>>(W1, b1, W2, b2, out);
}

// round 2
// speedup vs baseline: 1.7290x; 1.7290x over previous
#include <cuda_runtime.h>
#include <math.h>

#define Nn 50000
#define Ee 1600000
#define Gg 64
#define NB 49   // ceil(Nn/1024)

// ---------------- device scratch ----------------
__device__ float g_h[Nn*64];
__device__ float g_Q[Nn*64];
__device__ float g_K[Nn*64];
__device__ float g_V[Nn*64];
__device__ float g_S[Nn*64];
__device__ float g_U[Nn*64];        // u[node][2l] pairs for q.e folding
__device__ int   g_deg[Nn];
__device__ int   g_rowptr[Nn+1];
__device__ int   g_cursor[Nn];
__device__ int   g_bsum[64];
__device__ int2  g_perm[Ee];        // {src node, edge id}, CSR(dst)-ordered
__device__ float g_pool[Gg*64];
__device__ int   g_cnt[Gg];

// ---------------- zero ----------------
__global__ void zero_kernel() {
    int i = blockIdx.x * blockDim.x + threadIdx.x;
    const int total = Nn + Gg + Gg*64;
    for (; i < total; i += gridDim.x * blockDim.x) {
        if (i < Nn)            g_deg[i] = 0;
        else if (i < Nn + Gg)  g_cnt[i - Nn] = 0;
        else                   g_pool[i - Nn - Gg] = 0.f;
    }
}

// ---------------- degree histogram ----------------
__global__ void hist_kernel(const int* __restrict__ dst) {
    int e = blockIdx.x * blockDim.x + threadIdx.x;
    if (e < Ee) atomicAdd(&g_deg[dst[e]], 1);
}

// ---------------- two-level scan ----------------
__global__ void scanA_kernel() {
    __shared__ int sh[1024];
    int tid = threadIdx.x;
    int i = blockIdx.x * 1024 + tid;
    int v = (i < Nn) ? g_deg[i] : 0;
    sh[tid] = v;
    __syncthreads();
    for (int off = 1; off < 1024; off <<= 1) {
        int t = (tid >= off) ? sh[tid - off] : 0;
        __syncthreads();
        sh[tid] += t;
        __syncthreads();
    }
    if (i < Nn) g_rowptr[i] = sh[tid] - v;   // block-local exclusive
    if (tid == 1023) g_bsum[blockIdx.x] = sh[1023];
}
__global__ void scanB_kernel() {
    if (threadIdx.x == 0) {
        int s = 0;
        for (int b = 0; b < NB; b++) { int t = g_bsum[b]; g_bsum[b] = s; s += t; }
    }
}
__global__ void scanC_kernel() {
    int i = blockIdx.x * blockDim.x + threadIdx.x;
    if (i < Nn) {
        int r = g_rowptr[i] + g_bsum[i >> 10];
        g_rowptr[i] = r;
        g_cursor[i] = r;
    }
    if (i == 0) g_rowptr[Nn] = Ee;
}

// ---------------- scatter edge ids into CSR(dst) order ----------------
__global__ void scatter_kernel(const int* __restrict__ src,
                               const int* __restrict__ dst) {
    int e = blockIdx.x * blockDim.x + threadIdx.x;
    if (e >= Ee) return;
    int d = dst[e];
    int p = atomicAdd(&g_cursor[d], 1);
    g_perm[p] = make_int2(src[e], e);
}

// ---------------- input MLP: h = relu(x @ Wn + bn) ----------------
__global__ void node_in_kernel(const float* __restrict__ x,
                               const float* __restrict__ Wn,
                               const float* __restrict__ bn) {
    __shared__ float Wsm[32*64];
    __shared__ float bsm[64];
    __shared__ float rows[4*32];
    for (int i = threadIdx.x; i < 32*64; i += 256) Wsm[i] = Wn[i];
    if (threadIdx.x < 64) bsm[threadIdx.x] = bn[threadIdx.x];
    int c = threadIdx.x & 63, sub = threadIdx.x >> 6;
    int base = blockIdx.x * 64;
    for (int g = 0; g < 16; g++) {
        __syncthreads();
        if (threadIdx.x < 128) {
            int node = base + g*4 + (threadIdx.x >> 5);
            if (node < Nn) rows[threadIdx.x] = x[node*32 + (threadIdx.x & 31)];
        }
        __syncthreads();
        int node = base + g*4 + sub;
        if (node < Nn) {
            float acc = bsm[c];
            #pragma unroll
            for (int k = 0; k < 32; k++) acc = fmaf(rows[sub*32 + k], Wsm[k*64 + c], acc);
            g_h[node*64 + c] = fmaxf(acc, 0.f);
        }
    }
}

// ---------------- fused Q,K,U: one pass over h ----------------
__global__ void qku_kernel(const float* __restrict__ Wq, const float* __restrict__ bq,
                           const float* __restrict__ Wk, const float* __restrict__ bk,
                           const float* __restrict__ Wel) {
    __shared__ float WQs[4096], WKs[4096];
    __shared__ float WEsT[1024];    // WEsT[ch*16 + j] = We[j][ch]
    __shared__ float bQs[64], bKs[64];
    __shared__ float rows[256], Qs[256];
    for (int i = threadIdx.x; i < 4096; i += 256) { WQs[i] = Wq[i]; WKs[i] = Wk[i]; }
    for (int i = threadIdx.x; i < 1024; i += 256) {
        int ch = i >> 4, j = i & 15;
        WEsT[i] = Wel[j*64 + ch];
    }
    if (threadIdx.x < 64) { bQs[threadIdx.x] = bq[threadIdx.x]; bKs[threadIdx.x] = bk[threadIdx.x]; }
    int c = threadIdx.x & 63, sub = threadIdx.x >> 6;
    int base = blockIdx.x * 64;
    for (int g = 0; g < 16; g++) {
        __syncthreads();
        int node = base + g*4 + sub;
        if (node < Nn) rows[sub*64 + c] = g_h[node*64 + c];
        __syncthreads();
        if (node < Nn) {
            float aq = bQs[c], ak = bKs[c];
            #pragma unroll
            for (int k = 0; k < 64; k++) {
                float hk = rows[sub*64 + k];
                aq = fmaf(hk, WQs[k*64 + c], aq);
                ak = fmaf(hk, WKs[k*64 + c], ak);
            }
            g_Q[node*64 + c] = aq;
            g_K[node*64 + c] = ak;
            Qs[sub*64 + c] = aq;
        }
        __syncthreads();
        if (node < Nn) {
            int hh = c >> 4, j = c & 15;
            float u = 0.f;
            #pragma unroll
            for (int cc = 0; cc < 16; cc++)
                u = fmaf(Qs[sub*64 + 16*hh + cc], WEsT[(16*hh + cc)*16 + j], u);
            g_U[node*64 + c] = u;   // layout: u[node][h*16+j]
        }
    }
}

// ---------------- fused V,S: one pass over h ----------------
__global__ void vs_kernel(const float* __restrict__ Wv, const float* __restrict__ bv,
                          const float* __restrict__ Ws, const float* __restrict__ bs) {
    __shared__ float WVs[4096], WSs[4096];
    __shared__ float bVs[64], bSs[64];
    __shared__ float rows[256];
    for (int i = threadIdx.x; i < 4096; i += 256) { WVs[i] = Wv[i]; WSs[i] = Ws[i]; }
    if (threadIdx.x < 64) { bVs[threadIdx.x] = bv[threadIdx.x]; bSs[threadIdx.x] = bs[threadIdx.x]; }
    int c = threadIdx.x & 63, sub = threadIdx.x >> 6;
    int base = blockIdx.x * 64;
    for (int g = 0; g < 16; g++) {
        __syncthreads();
        int node = base + g*4 + sub;
        if (node < Nn) rows[sub*64 + c] = g_h[node*64 + c];
        __syncthreads();
        if (node < Nn) {
            float av = bVs[c], as = bSs[c];
            #pragma unroll
            for (int k = 0; k < 64; k++) {
                float hk = rows[sub*64 + k];
                av = fmaf(hk, WVs[k*64 + c], av);
                as = fmaf(hk, WSs[k*64 + c], as);
            }
            g_V[node*64 + c] = av;
            g_S[node*64 + c] = as;
        }
    }
}

// ---------------- attention: warp per dst, online softmax, edge-embedding factored out ----------------
__global__ void attn_kernel(const float* __restrict__ eattr,
                            const float* __restrict__ Wel) {
    __shared__ float WEs[1024];   // We[j*64+c]
    for (int i = threadIdx.x; i < 1024; i += 256) WEs[i] = Wel[i];
    __syncthreads();

    int wid  = (blockIdx.x * blockDim.x + threadIdx.x) >> 5;
    int lane = threadIdx.x & 31;
    if (wid >= Nn) return;

    int hh = lane >> 3;            // head
    int d2 = (lane & 7) * 2;       // eattr dim pair for aw accumulation

    float2 q = *(const float2*)(g_Q + (size_t)wid*64 + 2*lane);
    float2 u = *(const float2*)(g_U + (size_t)wid*64 + 2*lane);  // u[h][2(l&7)] == offset 2l

    int beg = g_rowptr[wid], end = g_rowptr[wid + 1];
    float m = -INFINITY, dsum = 0.f;
    float avx = 0.f, avy = 0.f, awx = 0.f, awy = 0.f;

    int i = beg;
    for (; i + 2 <= end; i += 2) {
        int2 p0 = g_perm[i];
        int2 p1 = g_perm[i + 1];
        float2 k0 = *(const float2*)(g_K + (size_t)p0.x*64 + 2*lane);
        float2 k1 = *(const float2*)(g_K + (size_t)p1.x*64 + 2*lane);
        float2 v0 = *(const float2*)(g_V + (size_t)p0.x*64 + 2*lane);
        float2 v1 = *(const float2*)(g_V + (size_t)p1.x*64 + 2*lane);
        float2 e0 = *(const float2*)(eattr + (size_t)p0.y*16 + d2);
        float2 e1 = *(const float2*)(eattr + (size_t)p1.y*16 + d2);

        float s0 = q.x*k0.x + q.y*k0.y + u.x*e0.x + u.y*e0.y;
        float s1 = q.x*k1.x + q.y*k1.y + u.x*e1.x + u.y*e1.y;
        s0 += __shfl_xor_sync(0xffffffffu, s0, 1);
        s1 += __shfl_xor_sync(0xffffffffu, s1, 1);
        s0 += __shfl_xor_sync(0xffffffffu, s0, 2);
        s1 += __shfl_xor_sync(0xffffffffu, s1, 2);
        s0 += __shfl_xor_sync(0xffffffffu, s0, 4);
        s1 += __shfl_xor_sync(0xffffffffu, s1, 4);
        float a0 = s0 * 0.25f, a1 = s1 * 0.25f;

        float mn = fmaxf(m, fmaxf(a0, a1));
        float corr = __expf(m - mn);
        float w0 = __expf(a0 - mn);
        float w1 = __expf(a1 - mn);
        dsum = dsum*corr + w0 + w1;
        avx = avx*corr + w0*v0.x + w1*v1.x;
        avy = avy*corr + w0*v0.y + w1*v1.y;
        awx = awx*corr + w0*e0.x + w1*e1.x;
        awy = awy*corr + w0*e0.y + w1*e1.y;
        m = mn;
    }
    if (i < end) {
        int2 p0 = g_perm[i];
        float2 k0 = *(const float2*)(g_K + (size_t)p0.x*64 + 2*lane);
        float2 v0 = *(const float2*)(g_V + (size_t)p0.x*64 + 2*lane);
        float2 e0 = *(const float2*)(eattr + (size_t)p0.y*16 + d2);
        float s0 = q.x*k0.x + q.y*k0.y + u.x*e0.x + u.y*e0.y;
        s0 += __shfl_xor_sync(0xffffffffu, s0, 1);
        s0 += __shfl_xor_sync(0xffffffffu, s0, 2);
        s0 += __shfl_xor_sync(0xffffffffu, s0, 4);
        float a0 = s0 * 0.25f;
        float mn = fmaxf(m, a0);
        float corr = __expf(m - mn);
        float w0 = __expf(a0 - mn);
        dsum = dsum*corr + w0;
        avx = avx*corr + w0*v0.x;
        avy = avy*corr + w0*v0.y;
        awx = awx*corr + w0*e0.x;
        awy = awy*corr + w0*e0.y;
        m = mn;
    }

    // apply We to the weighted-eattr accumulator (per node, not per edge)
    float ox = avx, oy = avy;
    #pragma unroll
    for (int jj = 0; jj < 8; jj++) {
        int srcl = (hh << 3) + jj;
        float bx = __shfl_sync(0xffffffffu, awx, srcl);   // aw[h][2jj]
        float by = __shfl_sync(0xffffffffu, awy, srcl);   // aw[h][2jj+1]
        ox = fmaf(bx, WEs[(2*jj)*64 + 2*lane],     ox);
        oy = fmaf(bx, WEs[(2*jj)*64 + 2*lane + 1], oy);
        ox = fmaf(by, WEs[(2*jj+1)*64 + 2*lane],     ox);
        oy = fmaf(by, WEs[(2*jj+1)*64 + 2*lane + 1], oy);
    }
    float inv = 1.f / (dsum + 1e-16f);
    float2 sv = *(const float2*)(g_S + (size_t)wid*64 + 2*lane);
    float o0 = fmaxf(fmaf(ox, inv, sv.x), 0.f);
    float o1 = fmaxf(fmaf(oy, inv, sv.y), 0.f);
    float2* hp = (float2*)(g_h + (size_t)wid*64 + 2*lane);
    float2 hv = *hp;
    hv.x += o0; hv.y += o1;
    *hp = hv;
}

// ---------------- pool: sorted-batch run-length accumulate ----------------
__global__ void pool_kernel(const int* __restrict__ batch) {
    int c = threadIdx.x & 63;
    int sub = threadIdx.x >> 6;
    int start = blockIdx.x * 1024 + sub * 256;
    if (start >= Nn) return;
    int end = min(start + 256, Nn);
    int gprev = batch[start];
    float acc = 0.f;
    int cnt = 0;
    for (int node = start; node < end; node++) {
        int g = batch[node];
        float v = g_h[(size_t)node*64 + c];
        if (g != gprev) {
            atomicAdd(&g_pool[gprev*64 + c], acc);
            if (c == 0) atomicAdd(&g_cnt[gprev], cnt);
            acc = 0.f; cnt = 0; gprev = g;
        }
        acc += v; cnt++;
    }
    atomicAdd(&g_pool[gprev*64 + c], acc);
    if (c == 0) atomicAdd(&g_cnt[gprev], cnt);
}

// ---------------- head MLP ----------------
__global__ void final_kernel(const float* __restrict__ W1, const float* __restrict__ b1,
                             const float* __restrict__ W2, const float* __restrict__ b2,
                             float* __restrict__ out) {
    int g = blockIdx.x;
    int j = threadIdx.x;
    float invc = 1.f / fmaxf((float)g_cnt[g], 1.f);
    float acc = b1[j];
    #pragma unroll
    for (int k = 0; k < 64; k++)
        acc = fmaf(g_pool[g*64 + k] * invc, W1[k*32 + j], acc);
    acc = fmaxf(acc, 0.f);
    float t = acc * W2[j];
    #pragma unroll
    for (int o = 16; o > 0; o >>= 1) t += __shfl_xor_sync(0xffffffffu, t, o);
    if (j == 0) out[g] = t + b2[0];
}

// ---------------- launch ----------------
extern "C" void kernel_launch(void* const* d_in, const int* in_sizes, int n_in,
                              void* d_out, int out_size) {
    const float* x     = (const float*)d_in[0];
    const int*   ei    = (const int*)  d_in[1];
    const float* eattr = (const float*)d_in[2];
    const int*   batch = (const int*)  d_in[3];
    const float* Wn = (const float*)d_in[4];  const float* bn = (const float*)d_in[5];
    const float* Wq = (const float*)d_in[6];  const float* bq = (const float*)d_in[7];
    const float* Wk = (const float*)d_in[8];  const float* bk = (const float*)d_in[9];
    const float* Wv = (const float*)d_in[10]; const float* bv = (const float*)d_in[11];
    const float* We = (const float*)d_in[12];
    const float* Ws = (const float*)d_in[13]; const float* bs = (const float*)d_in[14];
    const float* W1 = (const float*)d_in[15]; const float* b1 = (const float*)d_in[16];
    const float* W2 = (const float*)d_in[17]; const float* b2 = (const float*)d_in[18];
    float* out = (float*)d_out;

    const int* src = ei;
    const int* dst = ei + Ee;

    zero_kernel<<<64, 256>>>();
    hist_kernel<<<(Ee + 255)/256, 256>>>(dst);
    scanA_kernel<<<NB, 1024>>>();
    scanB_kernel<<<1, 32>>>();
    scanC_kernel<<<(Nn + 255)/256, 256>>>();
    scatter_kernel<<<(Ee + 255)/256, 256>>>(src, dst);
    node_in_kernel<<<(Nn + 63)/64, 256>>>(x, Wn, bn);

    for (int l = 0; l < 3; l++) {
        const float* Wql = Wq + (size_t)l*64*64; const float* bql = bq + (size_t)l*64;
        const float* Wkl = Wk + (size_t)l*64*64; const float* bkl = bk + (size_t)l*64;
        const float* Wvl = Wv + (size_t)l*64*64; const float* bvl = bv + (size_t)l*64;
        const float* Wsl = Ws + (size_t)l*64*64; const float* bsl = bs + (size_t)l*64;
        const float* Wel = We + (size_t)l*16*64;
        int gb = (Nn + 63) / 64;
        qku_kernel<<<gb, 256>>>(Wql, bql, Wkl, bkl, Wel);
        vs_kernel<<<gb, 256>>>(Wvl, bvl, Wsl, bsl);
        attn_kernel<<<(Nn*32 + 255)/256, 256>>>(eattr, Wel);
    }

    pool_kernel<<<(Nn + 1023)/1024, 256>>>(batch);
    final_kernel<<<Gg, 32>>>(W1, b1, W2, b2, out);
}